// round 2
// baseline (speedup 1.0000x reference)
#include <cuda_runtime.h>
#include <cstdint>

#define MODELS 8
#define BATCH 65536
#define CHOICE 100
#define CPB 128                          // customers per block
#define THREADS 128
#define NBLK (BATCH / CPB)               // 512
#define NTILES (2 + MODELS)              // y, x, z0..z7
#define TILE_F4 (CPB * CHOICE / 4)       // 3200 float4 per tile
#define F4_PER_THREAD (TILE_F4 / THREADS)// 25
#define SMEM_BYTES (2 * TILE_F4 * 16)    // 102400

__device__ float g_partials[NBLK];
__device__ unsigned int g_count;         // zero-init; finisher resets to 0

__device__ __forceinline__ void cp_async16(uint32_t dst_smem, const void* src) {
    asm volatile("cp.async.cg.shared.global [%0], [%1], 16;\n"
                 :: "r"(dst_smem), "l"(src));
}
__device__ __forceinline__ void cp_commit() {
    asm volatile("cp.async.commit_group;\n");
}
__device__ __forceinline__ void cp_wait1() {
    asm volatile("cp.async.wait_group 1;\n");
}
__device__ __forceinline__ void cp_wait0() {
    asm volatile("cp.async.wait_group 0;\n");
}

extern "C" __global__ void __launch_bounds__(THREADS, 2)
mmnl_main(const float* __restrict__ x, const float* __restrict__ y,
          const float* __restrict__ z, const float* __restrict__ alpha,
          const float* __restrict__ u_prev, const float* __restrict__ u,
          float* __restrict__ out)
{
    extern __shared__ float4 sbuf[];     // double buffer: 2 * TILE_F4 float4
    const int tid = threadIdx.x;
    const int bid = blockIdx.x;
    const size_t base_f = (size_t)bid * (CPB * CHOICE);

    __shared__ float s_alpha[MODELS], s_eup[MODELS];
    __shared__ float s_eu;
    __shared__ bool  s_last;
    if (tid < MODELS) { s_alpha[tid] = alpha[tid]; s_eup[tid] = __expf(u_prev[tid]); }
    if (tid == MODELS) s_eu = __expf(u[0]);

    // tile k source: k=0 -> y, k=1 -> x, k>=2 -> z[k-2]
    const float* srcs[NTILES];
    srcs[0] = y + base_f;
    srcs[1] = x + base_f;
#pragma unroll
    for (int m = 0; m < MODELS; m++)
        srcs[2 + m] = z + (size_t)m * (BATCH * CHOICE) + base_f;

    uint32_t sb = (uint32_t)__cvta_generic_to_shared(sbuf);

    // issue one tile's copy into buffer b (per-thread 25 x 16B cp.async)
    auto issue = [&](int k, int b) {
        const float4* s4 = (const float4*)srcs[k];
        uint32_t d = sb + (uint32_t)b * (TILE_F4 * 16);
#pragma unroll
        for (int i = 0; i < F4_PER_THREAD; i++) {
            int idx = i * THREADS + tid;
            cp_async16(d + (uint32_t)idx * 16u, s4 + idx);
        }
        cp_commit();
    };

    issue(0, 0);

    int   c_star = -1;
    float sex = 0.f, xy = 0.f, g = 0.f;

    for (int k = 0; k < NTILES; k++) {
        if (k + 1 < NTILES) { issue(k + 1, (k + 1) & 1); cp_wait1(); }
        else                { cp_wait0(); }
        __syncthreads();     // tile k fully visible to all threads

        const float4* B4 = sbuf + (size_t)(k & 1) * TILE_F4 + (size_t)tid * F4_PER_THREAD;
        const float*  Bf = (const float*)(sbuf + (size_t)(k & 1) * TILE_F4);

        if (k == 0) {
            // y tile: find one-hot index (or -1 if no purchase)
            int cs = -1;
#pragma unroll
            for (int j = 0; j < F4_PER_THREAD; j++) {
                float4 v = B4[j];
                if (v.x > 0.5f) cs = 4 * j + 0;
                if (v.y > 0.5f) cs = 4 * j + 1;
                if (v.z > 0.5f) cs = 4 * j + 2;
                if (v.w > 0.5f) cs = 4 * j + 3;
            }
            c_star = cs;
        } else {
            float a0 = 0.f, a1 = 0.f;
#pragma unroll
            for (int j = 0; j < F4_PER_THREAD; j++) {
                float4 v = B4[j];
                a0 += __expf(v.x); a1 += __expf(v.y);
                a0 += __expf(v.z); a1 += __expf(v.w);
            }
            float acc  = a0 + a1;
            float pick = Bf[tid * CHOICE + (c_star >= 0 ? c_star : 0)];
            if (k == 1) {
                sex = acc; xy = pick;
            } else {
                int   m   = k - 2;
                float eup = s_eup[m];
                float num = (c_star >= 0) ? __expf(pick) : eup;
                g += s_alpha[m] * num / (eup + acc);
            }
        }
        __syncthreads();     // done reading buf[k&1] before it is refilled
    }

    // per-customer term
    float eu   = s_eu;
    float numx = (c_star >= 0) ? __expf(xy) : eu;
    float tval = numx / ((eu + sex) * g);

    // block tree reduction (deterministic), reuse smem buffer
    float* red = (float*)sbuf;
    red[tid] = tval;
    __syncthreads();
#pragma unroll
    for (int s = THREADS / 2; s > 0; s >>= 1) {
        if (tid < s) red[tid] += red[tid + s];
        __syncthreads();
    }

    if (tid == 0) {
        g_partials[bid] = red[0];
        __threadfence();
        s_last = (atomicAdd(&g_count, 1u) == (unsigned)(NBLK - 1));
    }
    __syncthreads();

    if (s_last) {
        __threadfence();
        float a = 0.f;
        // fixed-order accumulation -> deterministic
        for (int i = tid; i < NBLK; i += THREADS) a += __ldcg(&g_partials[i]);
        red[tid] = a;
        __syncthreads();
#pragma unroll
        for (int s = THREADS / 2; s > 0; s >>= 1) {
            if (tid < s) red[tid] += red[tid + s];
            __syncthreads();
        }
        if (tid == 0) {
            out[0]  = -red[0] / (float)BATCH;
            g_count = 0;   // reset for next graph replay
        }
    }
}

extern "C" void kernel_launch(void* const* d_in, const int* in_sizes, int n_in,
                              void* d_out, int out_size)
{
    const float* x      = (const float*)d_in[0];
    const float* y      = (const float*)d_in[1];
    const float* z      = (const float*)d_in[2];
    const float* alpha  = (const float*)d_in[3];
    const float* u_prev = (const float*)d_in[4];
    const float* u      = (const float*)d_in[5];
    float* out = (float*)d_out;

    static bool attr_set = false;
    if (!attr_set) {
        cudaFuncSetAttribute(mmnl_main,
                             cudaFuncAttributeMaxDynamicSharedMemorySize,
                             SMEM_BYTES);
        attr_set = true;
    }
    mmnl_main<<<NBLK, THREADS, SMEM_BYTES>>>(x, y, z, alpha, u_prev, u, out);
}

// round 3
// speedup vs baseline: 1.3106x; 1.3106x over previous
#include <cuda_runtime.h>
#include <cstdint>

#define MODELS 8
#define BATCH 65536
#define CHOICE 100
#define CPB 128                           // customers per block
#define THREADS 256                       // 2 threads per customer
#define NBLK (BATCH / CPB)                // 512
#define NTILES (2 + MODELS)               // y, x, z0..z7
#define TILE_F4 (CPB * CHOICE / 4)        // 3200 float4 per tile
#define CP_ITERS ((TILE_F4 + THREADS - 1) / THREADS)   // 13
#define SMEM_BYTES (2 * TILE_F4 * 16)     // 102400

__device__ float g_partials[NBLK];
__device__ unsigned int g_count;          // zero-init; finisher resets to 0

__device__ __forceinline__ void cp_async16(uint32_t dst_smem, const void* src) {
    asm volatile("cp.async.cg.shared.global [%0], [%1], 16;\n"
                 :: "r"(dst_smem), "l"(src));
}
__device__ __forceinline__ void cp_commit() {
    asm volatile("cp.async.commit_group;\n");
}
__device__ __forceinline__ void cp_wait1() {
    asm volatile("cp.async.wait_group 1;\n");
}
__device__ __forceinline__ void cp_wait0() {
    asm volatile("cp.async.wait_group 0;\n");
}

extern "C" __global__ void __launch_bounds__(THREADS, 2)
mmnl_main(const float* __restrict__ x, const float* __restrict__ y,
          const float* __restrict__ z, const float* __restrict__ alpha,
          const float* __restrict__ u_prev, const float* __restrict__ u,
          float* __restrict__ out)
{
    extern __shared__ float4 sbuf[];      // double buffer: 2 * TILE_F4 float4
    const int tid = threadIdx.x;
    const int bid = blockIdx.x;
    const size_t base_f = (size_t)bid * (CPB * CHOICE);

    __shared__ float s_alpha[MODELS], s_eup[MODELS];
    __shared__ float s_eu;
    __shared__ bool  s_last;
    if (tid < MODELS) { s_alpha[tid] = alpha[tid]; s_eup[tid] = __expf(u_prev[tid]); }
    if (tid == MODELS) s_eu = __expf(u[0]);

    const float* srcs[NTILES];
    srcs[0] = y + base_f;
    srcs[1] = x + base_f;
#pragma unroll
    for (int m = 0; m < MODELS; m++)
        srcs[2 + m] = z + (size_t)m * (BATCH * CHOICE) + base_f;

    uint32_t sb = (uint32_t)__cvta_generic_to_shared(sbuf);

    auto issue = [&](int k, int b) {
        const float4* s4 = (const float4*)srcs[k];
        uint32_t d = sb + (uint32_t)b * (TILE_F4 * 16);
#pragma unroll
        for (int i = 0; i < CP_ITERS; i++) {
            int idx = i * THREADS + tid;
            if (idx < TILE_F4)
                cp_async16(d + (uint32_t)idx * 16u, s4 + idx);
        }
        cp_commit();
    };

    issue(0, 0);

    const int c  = tid >> 1;              // customer within block
    const int h  = tid & 1;               // half: 0 -> f4 [0,13), 1 -> f4 [13,25)
    const int j0 = h ? 13 : 0;
    const int jn = h ? 12 : 13;

    int   c_star = 0;
    bool  has    = false;
    float sex = 0.f, xy = 0.f, g = 0.f;

    for (int k = 0; k < NTILES; k++) {
        if (k + 1 < NTILES) { issue(k + 1, (k + 1) & 1); cp_wait1(); }
        else                { cp_wait0(); }
        __syncthreads();

        const float4* row4 =
            sbuf + (size_t)(k & 1) * TILE_F4 + (size_t)c * (CHOICE / 4) + j0;
        const float* rowf =
            (const float*)(sbuf + (size_t)(k & 1) * TILE_F4) + (size_t)c * CHOICE;

        if (k == 0) {
            // y: branch-free one-hot locate on this half
            float sy = 0.f, sd = 0.f;
#pragma unroll 13
            for (int j = 0; j < jn; j++) {
                float4 v = row4[j];
                float cb = (float)(4 * (j0 + j));
                sy += v.x + v.y + v.z + v.w;
                sd  = fmaf(v.x, cb,       sd);
                sd  = fmaf(v.y, cb + 1.f, sd);
                sd  = fmaf(v.z, cb + 2.f, sd);
                sd  = fmaf(v.w, cb + 3.f, sd);
            }
            sy += __shfl_xor_sync(0xffffffffu, sy, 1);
            sd += __shfl_xor_sync(0xffffffffu, sd, 1);
            has    = (sy > 0.5f);
            c_star = has ? (int)rintf(sd) : 0;
        } else {
            float a0 = 0.f, a1 = 0.f;
#pragma unroll 13
            for (int j = 0; j < jn; j++) {
                float4 v = row4[j];
                a0 += __expf(v.x) + __expf(v.z);
                a1 += __expf(v.y) + __expf(v.w);
            }
            float acc = a0 + a1;
            acc += __shfl_xor_sync(0xffffffffu, acc, 1);
            float pick = rowf[c_star];
            if (k == 1) {
                sex = acc; xy = pick;
            } else {
                int   m   = k - 2;
                float eup = s_eup[m];
                float num = has ? __expf(pick) : eup;
                g += s_alpha[m] * num / (eup + acc);
            }
        }
        __syncthreads();
    }

    float eu   = s_eu;
    float numx = has ? __expf(xy) : eu;
    float tval = numx / ((eu + sex) * g);

    // block tree reduction (deterministic), even lanes carry the value
    float* red = (float*)sbuf;
    red[tid] = (h == 0) ? tval : 0.f;
    __syncthreads();
#pragma unroll
    for (int s = THREADS / 2; s > 0; s >>= 1) {
        if (tid < s) red[tid] += red[tid + s];
        __syncthreads();
    }

    if (tid == 0) {
        g_partials[bid] = red[0];
        __threadfence();
        s_last = (atomicAdd(&g_count, 1u) == (unsigned)(NBLK - 1));
    }
    __syncthreads();

    if (s_last) {
        __threadfence();
        float a = 0.f;
        for (int i = tid; i < NBLK; i += THREADS) a += __ldcg(&g_partials[i]);
        red[tid] = a;
        __syncthreads();
#pragma unroll
        for (int s = THREADS / 2; s > 0; s >>= 1) {
            if (tid < s) red[tid] += red[tid + s];
            __syncthreads();
        }
        if (tid == 0) {
            out[0]  = -red[0] / (float)BATCH;
            g_count = 0;   // reset for next graph replay
        }
    }
}

extern "C" void kernel_launch(void* const* d_in, const int* in_sizes, int n_in,
                              void* d_out, int out_size)
{
    const float* x      = (const float*)d_in[0];
    const float* y      = (const float*)d_in[1];
    const float* z      = (const float*)d_in[2];
    const float* alpha  = (const float*)d_in[3];
    const float* u_prev = (const float*)d_in[4];
    const float* u      = (const float*)d_in[5];
    float* out = (float*)d_out;

    static bool attr_set = false;
    if (!attr_set) {
        cudaFuncSetAttribute(mmnl_main,
                             cudaFuncAttributeMaxDynamicSharedMemorySize,
                             SMEM_BYTES);
        attr_set = true;
    }
    mmnl_main<<<NBLK, THREADS, SMEM_BYTES>>>(x, y, z, alpha, u_prev, u, out);
}